// round 8
// baseline (speedup 1.0000x reference)
#include <cuda_runtime.h>

// LSTM_16638703305445: B=4096, T=365, IN=32, H=256, OUT=1
// Persistent per-CTA batch-sliced LSTM scan. 256 CTAs x 256 threads, 2 CTA/SM.
// Thread j owns hidden unit j for the CTA's 16 batch rows; gates accumulate
// as packed f32x2 pairs (FFMA2). R5: c-state in smem, no temp arrays, bias
// rematerialized per step, x double-buffered+prefetched -> no register spills.

#define T_STEPS 365
#define IN_DIM  32
#define H_DIM   256
#define B_BLK   16   // batch rows per CTA
#define NB      8    // f32x2 pairs per thread (16 batch rows)

typedef unsigned long long u64;

__device__ __forceinline__ u64 fma2(u64 a, u64 b, u64 c) {
    u64 d;
    asm("fma.rn.f32x2 %0, %1, %2, %3;" : "=l"(d) : "l"(a), "l"(b), "l"(c));
    return d;
}
__device__ __forceinline__ u64 bc2(float x) {
    u64 d;
    asm("mov.b64 %0, {%1, %1};" : "=l"(d) : "f"(x));
    return d;
}
__device__ __forceinline__ void unpack2(u64 v, float& lo, float& hi) {
    asm("mov.b64 {%0, %1}, %2;" : "=f"(lo), "=f"(hi) : "l"(v));
}
__device__ __forceinline__ float sigm(float x) {
    return __fdividef(1.0f, 1.0f + __expf(-x));
}
__device__ __forceinline__ float tanh_acc(float x) {
    float a = fabsf(x);
    float e = __expf(-2.0f * a);
    float r = __fdividef(1.0f - e, 1.0f + e);
    return copysignf(r, x);
}
__device__ __forceinline__ float f4c(const float4 v, int kk) {
    return kk == 0 ? v.x : kk == 1 ? v.y : kk == 2 ? v.z : v.w;
}

__global__ void __launch_bounds__(256, 2)
lstm_scan_kernel(const float* __restrict__ xd,    // [B, T, IN]
                 const float* __restrict__ w_ih,  // [4H, IN]
                 const float* __restrict__ w_hh,  // [4H, H]
                 const float* __restrict__ bias,  // [4H]
                 const float* __restrict__ w_out, // [1, H]
                 const float* __restrict__ b_out, // [1]
                 float* __restrict__ out)         // [B, 1]
{
    __shared__ float h_s[H_DIM * B_BLK];      // [k][b], 16 KB
    __shared__ float x_s[2][IN_DIM * B_BLK];  // [i][b], 2x2 KB, double-buffered
    __shared__ float c_s[B_BLK * H_DIM];      // [b][j], 16 KB (conflict-free)

    const int j  = threadIdx.x;          // hidden unit 0..255
    const int B0 = blockIdx.x * B_BLK;   // batch base for this CTA

    // init state
    #pragma unroll
    for (int b = 0; b < B_BLK; b++) h_s[j * B_BLK + b] = 0.0f;
    #pragma unroll
    for (int b = 0; b < B_BLK; b++) c_s[b * H_DIM + j] = 0.0f;

    // bias kept as 4 scalar floats; f32x2 broadcasts rebuilt per step (cheap)
    const float bi = bias[j];
    const float bf = bias[H_DIM + j];
    const float bg = bias[2 * H_DIM + j];
    const float bo = bias[3 * H_DIM + j];

    // W_hh row base in float4 units (row stride 64; gate offset 16384)
    const float4* Wb = (const float4*)w_hh + (size_t)j * (H_DIM / 4);
    // w_ih row base in float4 units (row stride 8; gate offset 2048)
    const float4* Ub = (const float4*)w_ih + (size_t)j * (IN_DIM / 4);

    // x-tile lane mapping (thread covers elements j and j+256 of the 512-elem tile)
    const int xb0 = j >> 5,         xi0 = j & 31;
    const int xb1 = (j + 256) >> 5, xi1 = (j + 256) & 31;
    const float* xp0 = xd + (size_t)(B0 + xb0) * (T_STEPS * IN_DIM) + xi0;
    const float* xp1 = xd + (size_t)(B0 + xb1) * (T_STEPS * IN_DIM) + xi1;

    // prefetch x(0)
    float xr0 = __ldg(xp0);
    float xr1 = __ldg(xp1);

    __syncthreads();

    for (int t = 0; t < T_STEPS; t++) {
        // stage prefetched x tile, transposed to [i][b]
        float* xbuf = x_s[t & 1];
        xbuf[xi0 * B_BLK + xb0] = xr0;
        xbuf[xi1 * B_BLK + xb1] = xr1;
        // prefetch x(t+1) — latency hidden under the K loop below
        {
            int tn = (t + 1 < T_STEPS) ? t + 1 : t;
            xr0 = __ldg(xp0 + tn * IN_DIM);
            xr1 = __ldg(xp1 + tn * IN_DIM);
        }
        __syncthreads();  // x ready; also orders previous step's h_s writes

        const u64 bi2 = bc2(bi), bf2 = bc2(bf), bg2 = bc2(bg), bo2 = bc2(bo);
        u64 ai[NB], af[NB], ag[NB], ao[NB];
        #pragma unroll
        for (int p = 0; p < NB; p++) { ai[p] = bi2; af[p] = bf2; ag[p] = bg2; ao[p] = bo2; }

        // ---- input projection: 8 chunks of 4 over IN=32
        #pragma unroll 2
        for (int kc = 0; kc < IN_DIM / 4; kc++) {
            float4 wi4 = __ldg(Ub + kc);
            float4 wf4 = __ldg(Ub + kc + 2048);
            float4 wg4 = __ldg(Ub + kc + 4096);
            float4 wo4 = __ldg(Ub + kc + 6144);
            #pragma unroll
            for (int kk = 0; kk < 4; kk++) {
                const ulonglong2* hp = (const ulonglong2*)(xbuf + (kc * 4 + kk) * B_BLK);
                const ulonglong2 h0 = hp[0], h1 = hp[1], h2 = hp[2], h3 = hp[3];
                const u64 wib = bc2(f4c(wi4, kk));
                const u64 wfb = bc2(f4c(wf4, kk));
                const u64 wgb = bc2(f4c(wg4, kk));
                const u64 wob = bc2(f4c(wo4, kk));
                ai[0] = fma2(h0.x, wib, ai[0]); af[0] = fma2(h0.x, wfb, af[0]);
                ag[0] = fma2(h0.x, wgb, ag[0]); ao[0] = fma2(h0.x, wob, ao[0]);
                ai[1] = fma2(h0.y, wib, ai[1]); af[1] = fma2(h0.y, wfb, af[1]);
                ag[1] = fma2(h0.y, wgb, ag[1]); ao[1] = fma2(h0.y, wob, ao[1]);
                ai[2] = fma2(h1.x, wib, ai[2]); af[2] = fma2(h1.x, wfb, af[2]);
                ag[2] = fma2(h1.x, wgb, ag[2]); ao[2] = fma2(h1.x, wob, ao[2]);
                ai[3] = fma2(h1.y, wib, ai[3]); af[3] = fma2(h1.y, wfb, af[3]);
                ag[3] = fma2(h1.y, wgb, ag[3]); ao[3] = fma2(h1.y, wob, ao[3]);
                ai[4] = fma2(h2.x, wib, ai[4]); af[4] = fma2(h2.x, wfb, af[4]);
                ag[4] = fma2(h2.x, wgb, ag[4]); ao[4] = fma2(h2.x, wob, ao[4]);
                ai[5] = fma2(h2.y, wib, ai[5]); af[5] = fma2(h2.y, wfb, af[5]);
                ag[5] = fma2(h2.y, wgb, ag[5]); ao[5] = fma2(h2.y, wob, ao[5]);
                ai[6] = fma2(h3.x, wib, ai[6]); af[6] = fma2(h3.x, wfb, af[6]);
                ag[6] = fma2(h3.x, wgb, ag[6]); ao[6] = fma2(h3.x, wob, ao[6]);
                ai[7] = fma2(h3.y, wib, ai[7]); af[7] = fma2(h3.y, wfb, af[7]);
                ag[7] = fma2(h3.y, wgb, ag[7]); ao[7] = fma2(h3.y, wob, ao[7]);
            }
        }

        // ---- recurrent projection: 64 chunks of 4 over H=256
        #pragma unroll 2
        for (int kc = 0; kc < H_DIM / 4; kc++) {
            float4 wi4 = __ldg(Wb + kc);
            float4 wf4 = __ldg(Wb + kc + 16384);
            float4 wg4 = __ldg(Wb + kc + 32768);
            float4 wo4 = __ldg(Wb + kc + 49152);
            #pragma unroll
            for (int kk = 0; kk < 4; kk++) {
                const ulonglong2* hp = (const ulonglong2*)(h_s + (kc * 4 + kk) * B_BLK);
                const ulonglong2 h0 = hp[0], h1 = hp[1], h2 = hp[2], h3 = hp[3];
                const u64 wib = bc2(f4c(wi4, kk));
                const u64 wfb = bc2(f4c(wf4, kk));
                const u64 wgb = bc2(f4c(wg4, kk));
                const u64 wob = bc2(f4c(wo4, kk));
                ai[0] = fma2(h0.x, wib, ai[0]); af[0] = fma2(h0.x, wfb, af[0]);
                ag[0] = fma2(h0.x, wgb, ag[0]); ao[0] = fma2(h0.x, wob, ao[0]);
                ai[1] = fma2(h0.y, wib, ai[1]); af[1] = fma2(h0.y, wfb, af[1]);
                ag[1] = fma2(h0.y, wgb, ag[1]); ao[1] = fma2(h0.y, wob, ao[1]);
                ai[2] = fma2(h1.x, wib, ai[2]); af[2] = fma2(h1.x, wfb, af[2]);
                ag[2] = fma2(h1.x, wgb, ag[2]); ao[2] = fma2(h1.x, wob, ao[2]);
                ai[3] = fma2(h1.y, wib, ai[3]); af[3] = fma2(h1.y, wfb, af[3]);
                ag[3] = fma2(h1.y, wgb, ag[3]); ao[3] = fma2(h1.y, wob, ao[3]);
                ai[4] = fma2(h2.x, wib, ai[4]); af[4] = fma2(h2.x, wfb, af[4]);
                ag[4] = fma2(h2.x, wgb, ag[4]); ao[4] = fma2(h2.x, wob, ao[4]);
                ai[5] = fma2(h2.y, wib, ai[5]); af[5] = fma2(h2.y, wfb, af[5]);
                ag[5] = fma2(h2.y, wgb, ag[5]); ao[5] = fma2(h2.y, wob, ao[5]);
                ai[6] = fma2(h3.x, wib, ai[6]); af[6] = fma2(h3.x, wfb, af[6]);
                ag[6] = fma2(h3.x, wgb, ag[6]); ao[6] = fma2(h3.x, wob, ao[6]);
                ai[7] = fma2(h3.y, wib, ai[7]); af[7] = fma2(h3.y, wfb, af[7]);
                ag[7] = fma2(h3.y, wgb, ag[7]); ao[7] = fma2(h3.y, wob, ao[7]);
            }
        }

        __syncthreads();  // everyone done reading h_s / x_s

        // ---- gate nonlinearities + state update + h write (c lives in smem)
        #pragma unroll
        for (int p = 0; p < NB; p++) {
            float i0, i1, f0, f1, g0, g1, o0, o1;
            unpack2(ai[p], i0, i1);
            unpack2(af[p], f0, f1);
            unpack2(ag[p], g0, g1);
            unpack2(ao[p], o0, o1);
            const int b0 = 2 * p, b1 = 2 * p + 1;
            {
                float iv = sigm(i0), fv = sigm(f0), gv = tanh_acc(g0), ov = sigm(o0);
                float cv = fv * c_s[b0 * H_DIM + j] + iv * gv;
                c_s[b0 * H_DIM + j] = cv;
                h_s[j * B_BLK + b0] = ov * tanh_acc(cv);
            }
            {
                float iv = sigm(i1), fv = sigm(f1), gv = tanh_acc(g1), ov = sigm(o1);
                float cv = fv * c_s[b1 * H_DIM + j] + iv * gv;
                c_s[b1 * H_DIM + j] = cv;
                h_s[j * B_BLK + b1] = ov * tanh_acc(cv);
            }
        }
    }

    __syncthreads();

    // ---- output head: out[b] = relu(sum_k h_T[b,k] * w_out[k] + b_out)
    {
        int b = j >> 4;   // 0..15
        int l = j & 15;   // 0..15
        float s = 0.0f;
        #pragma unroll
        for (int k = l; k < H_DIM; k += 16)
            s += h_s[k * B_BLK + b] * __ldg(&w_out[k]);
        #pragma unroll
        for (int off = 8; off > 0; off >>= 1)
            s += __shfl_down_sync(0xffffffffu, s, off);
        if (l == 0) {
            float r = s + __ldg(&b_out[0]);
            out[B0 + b] = r > 0.0f ? r : 0.0f;
        }
    }
}

extern "C" void kernel_launch(void* const* d_in, const int* in_sizes, int n_in,
                              void* d_out, int out_size) {
    // Identify inputs by element count (all distinct) — robust to ordering.
    const float *xd = nullptr, *w_ih = nullptr, *w_hh = nullptr;
    const float *bias = nullptr, *w_out = nullptr, *b_out = nullptr;
    for (int i = 0; i < n_in; i++) {
        switch (in_sizes[i]) {
            case 4096 * 365 * 32: xd    = (const float*)d_in[i]; break;  // 47841280
            case 1024 * 32:       w_ih  = (const float*)d_in[i]; break;  // 32768
            case 1024 * 256:      w_hh  = (const float*)d_in[i]; break;  // 262144
            case 1024:            bias  = (const float*)d_in[i]; break;
            case 256:             w_out = (const float*)d_in[i]; break;
            case 1:               b_out = (const float*)d_in[i]; break;
            default: break;
        }
    }
    float* out = (float*)d_out;
    lstm_scan_kernel<<<4096 / B_BLK, 256>>>(xd, w_ih, w_hh, bias, w_out, b_out, out);
}

// round 9
// speedup vs baseline: 1.6390x; 1.6390x over previous
#include <cuda_runtime.h>

// LSTM_16638703305445: B=4096, T=365, IN=32, H=256, OUT=1
// R8: weights pre-transposed into WT[k][gate*256 + j] so the scan's W loads
// are coalesced (1 L1tex wavefront per warp-load instead of 32). The R4/R7
// kernels were L1tex-wavefront-bound on per-row (uncoalesced) W reads.
// Persistent per-CTA batch-sliced scan: 256 CTAs x 256 threads, 2 CTA/SM.
// Thread j owns hidden unit j for 16 batch rows; gates accumulate as packed
// f32x2 pairs (FFMA2).

#define T_STEPS 365
#define IN_DIM  32
#define H_DIM   256
#define B_BLK   16   // batch rows per CTA
#define NB      8    // f32x2 pairs per thread (16 batch rows)
#define K_TOT   (H_DIM + IN_DIM)   // 288

typedef unsigned long long u64;

// Transposed weights: WT[k][g*256 + j]
//   k in [0,256):   w_hh column k      (WT[k][g*256+j] = w_hh[(g*256+j)*256 + k])
//   k in [256,288): w_ih column k-256  (WT[k][g*256+j] = w_ih[(g*256+j)*32 + k-256])
__device__ float g_WT[K_TOT * 1024];

__global__ void transpose_w_kernel(const float* __restrict__ w_ih,
                                   const float* __restrict__ w_hh) {
    int idx = blockIdx.x * blockDim.x + threadIdx.x;
    if (idx >= K_TOT * 1024) return;
    int k   = idx >> 10;        // 0..287
    int col = idx & 1023;       // g*256 + j
    float v;
    if (k < H_DIM) v = w_hh[(size_t)col * H_DIM + k];
    else           v = w_ih[(size_t)col * IN_DIM + (k - H_DIM)];
    g_WT[idx] = v;
}

__device__ __forceinline__ u64 fma2(u64 a, u64 b, u64 c) {
    u64 d;
    asm("fma.rn.f32x2 %0, %1, %2, %3;" : "=l"(d) : "l"(a), "l"(b), "l"(c));
    return d;
}
__device__ __forceinline__ u64 bc2(float x) {
    u64 d;
    asm("mov.b64 %0, {%1, %1};" : "=l"(d) : "f"(x));
    return d;
}
__device__ __forceinline__ void unpack2(u64 v, float& lo, float& hi) {
    asm("mov.b64 {%0, %1}, %2;" : "=f"(lo), "=f"(hi) : "l"(v));
}
__device__ __forceinline__ float sigm(float x) {
    return __fdividef(1.0f, 1.0f + __expf(-x));
}
__device__ __forceinline__ float tanh_acc(float x) {
    float a = fabsf(x);
    float e = __expf(-2.0f * a);
    float r = __fdividef(1.0f - e, 1.0f + e);
    return copysignf(r, x);
}

// One k-slice of the gate accumulation: 4 coalesced W loads + 16 h values
// (4 broadcast LDS.128) + 32 FFMA2.
#define GATE_K(wt_row, hrow)                                                   \
    {                                                                          \
        const float wi = __ldg((wt_row));                                      \
        const float wf = __ldg((wt_row) + 256);                                \
        const float wg = __ldg((wt_row) + 512);                                \
        const float wo = __ldg((wt_row) + 768);                                \
        const ulonglong2* hp = (const ulonglong2*)(hrow);                      \
        const ulonglong2 h0 = hp[0], h1 = hp[1], h2 = hp[2], h3 = hp[3];       \
        const u64 wib = bc2(wi), wfb = bc2(wf), wgb = bc2(wg), wob = bc2(wo);  \
        ai[0] = fma2(h0.x, wib, ai[0]); af[0] = fma2(h0.x, wfb, af[0]);        \
        ag[0] = fma2(h0.x, wgb, ag[0]); ao[0] = fma2(h0.x, wob, ao[0]);        \
        ai[1] = fma2(h0.y, wib, ai[1]); af[1] = fma2(h0.y, wfb, af[1]);        \
        ag[1] = fma2(h0.y, wgb, ag[1]); ao[1] = fma2(h0.y, wob, ao[1]);        \
        ai[2] = fma2(h1.x, wib, ai[2]); af[2] = fma2(h1.x, wfb, af[2]);        \
        ag[2] = fma2(h1.x, wgb, ag[2]); ao[2] = fma2(h1.x, wob, ao[2]);        \
        ai[3] = fma2(h1.y, wib, ai[3]); af[3] = fma2(h1.y, wfb, af[3]);        \
        ag[3] = fma2(h1.y, wgb, ag[3]); ao[3] = fma2(h1.y, wob, ao[3]);        \
        ai[4] = fma2(h2.x, wib, ai[4]); af[4] = fma2(h2.x, wfb, af[4]);        \
        ag[4] = fma2(h2.x, wgb, ag[4]); ao[4] = fma2(h2.x, wob, ao[4]);        \
        ai[5] = fma2(h2.y, wib, ai[5]); af[5] = fma2(h2.y, wfb, af[5]);        \
        ag[5] = fma2(h2.y, wgb, ag[5]); ao[5] = fma2(h2.y, wob, ao[5]);        \
        ai[6] = fma2(h3.x, wib, ai[6]); af[6] = fma2(h3.x, wfb, af[6]);        \
        ag[6] = fma2(h3.x, wgb, ag[6]); ao[6] = fma2(h3.x, wob, ao[6]);        \
        ai[7] = fma2(h3.y, wib, ai[7]); af[7] = fma2(h3.y, wfb, af[7]);        \
        ag[7] = fma2(h3.y, wgb, ag[7]); ao[7] = fma2(h3.y, wob, ao[7]);        \
    }

__global__ void __launch_bounds__(256, 2)
lstm_scan_kernel(const float* __restrict__ xd,    // [B, T, IN]
                 const float* __restrict__ bias,  // [4H]
                 const float* __restrict__ w_out, // [1, H]
                 const float* __restrict__ b_out, // [1]
                 float* __restrict__ out)         // [B, 1]
{
    __shared__ float h_s[H_DIM * B_BLK];      // [k][b], 16 KB
    __shared__ float x_s[2][IN_DIM * B_BLK];  // [i][b], 2x2 KB, double-buffered
    __shared__ float c_s[B_BLK * H_DIM];      // [b][j], 16 KB, conflict-free

    const int j  = threadIdx.x;          // hidden unit 0..255
    const int B0 = blockIdx.x * B_BLK;   // batch base for this CTA

    #pragma unroll
    for (int b = 0; b < B_BLK; b++) h_s[j * B_BLK + b] = 0.0f;
    #pragma unroll
    for (int b = 0; b < B_BLK; b++) c_s[b * H_DIM + j] = 0.0f;

    const float bi = bias[j];
    const float bf = bias[H_DIM + j];
    const float bg = bias[2 * H_DIM + j];
    const float bo = bias[3 * H_DIM + j];

    // Coalesced transposed-weight base: lane j reads wt[k*1024 + g*256 + j].
    const float* wt = g_WT + j;

    // x-tile lane mapping (thread covers elements j and j+256 of the 512-elem tile)
    const int xb0 = j >> 5,         xi0 = j & 31;
    const int xb1 = (j + 256) >> 5, xi1 = (j + 256) & 31;
    const float* xp0 = xd + (size_t)(B0 + xb0) * (T_STEPS * IN_DIM) + xi0;
    const float* xp1 = xd + (size_t)(B0 + xb1) * (T_STEPS * IN_DIM) + xi1;

    float xr0 = __ldg(xp0);
    float xr1 = __ldg(xp1);

    __syncthreads();

    for (int t = 0; t < T_STEPS; t++) {
        // stage prefetched x tile, transposed to [i][b]
        float* xbuf = x_s[t & 1];
        xbuf[xi0 * B_BLK + xb0] = xr0;
        xbuf[xi1 * B_BLK + xb1] = xr1;
        {   // prefetch x(t+1) — latency hidden under the K loop
            int tn = (t + 1 < T_STEPS) ? t + 1 : t;
            xr0 = __ldg(xp0 + tn * IN_DIM);
            xr1 = __ldg(xp1 + tn * IN_DIM);
        }
        __syncthreads();  // x ready; also orders previous step's h_s writes

        const u64 bi2 = bc2(bi), bf2 = bc2(bf), bg2 = bc2(bg), bo2 = bc2(bo);
        u64 ai[NB], af[NB], ag[NB], ao[NB];
        #pragma unroll
        for (int p = 0; p < NB; p++) { ai[p] = bi2; af[p] = bf2; ag[p] = bg2; ao[p] = bo2; }

        // ---- recurrent projection: k over H=256 (WT rows 0..255)
        #pragma unroll 4
        for (int k = 0; k < H_DIM; k++) {
            GATE_K(wt + k * 1024, h_s + k * B_BLK);
        }

        // ---- input projection: k over IN=32 (WT rows 256..287)
        #pragma unroll 4
        for (int k = 0; k < IN_DIM; k++) {
            GATE_K(wt + (H_DIM + k) * 1024, xbuf + k * B_BLK);
        }

        __syncthreads();  // everyone done reading h_s / x_s

        // ---- gate nonlinearities + state update + h write (c in smem)
        #pragma unroll
        for (int p = 0; p < NB; p++) {
            float i0, i1, f0, f1, g0, g1, o0, o1;
            unpack2(ai[p], i0, i1);
            unpack2(af[p], f0, f1);
            unpack2(ag[p], g0, g1);
            unpack2(ao[p], o0, o1);
            const int b0 = 2 * p, b1 = 2 * p + 1;
            {
                float iv = sigm(i0), fv = sigm(f0), gv = tanh_acc(g0), ov = sigm(o0);
                float cv = fv * c_s[b0 * H_DIM + j] + iv * gv;
                c_s[b0 * H_DIM + j] = cv;
                h_s[j * B_BLK + b0] = ov * tanh_acc(cv);
            }
            {
                float iv = sigm(i1), fv = sigm(f1), gv = tanh_acc(g1), ov = sigm(o1);
                float cv = fv * c_s[b1 * H_DIM + j] + iv * gv;
                c_s[b1 * H_DIM + j] = cv;
                h_s[j * B_BLK + b1] = ov * tanh_acc(cv);
            }
        }
    }

    __syncthreads();

    // ---- output head: out[b] = relu(sum_k h_T[b,k] * w_out[k] + b_out)
    {
        int b = j >> 4;   // 0..15
        int l = j & 15;   // 0..15
        float s = 0.0f;
        #pragma unroll
        for (int k = l; k < H_DIM; k += 16)
            s += h_s[k * B_BLK + b] * __ldg(&w_out[k]);
        #pragma unroll
        for (int off = 8; off > 0; off >>= 1)
            s += __shfl_down_sync(0xffffffffu, s, off);
        if (l == 0) {
            float r = s + __ldg(&b_out[0]);
            out[B0 + b] = r > 0.0f ? r : 0.0f;
        }
    }
}

extern "C" void kernel_launch(void* const* d_in, const int* in_sizes, int n_in,
                              void* d_out, int out_size) {
    // Identify inputs by element count (all distinct) — robust to ordering.
    const float *xd = nullptr, *w_ih = nullptr, *w_hh = nullptr;
    const float *bias = nullptr, *w_out = nullptr, *b_out = nullptr;
    for (int i = 0; i < n_in; i++) {
        switch (in_sizes[i]) {
            case 4096 * 365 * 32: xd    = (const float*)d_in[i]; break;  // 47841280
            case 1024 * 32:       w_ih  = (const float*)d_in[i]; break;  // 32768
            case 1024 * 256:      w_hh  = (const float*)d_in[i]; break;  // 262144
            case 1024:            bias  = (const float*)d_in[i]; break;
            case 256:             w_out = (const float*)d_in[i]; break;
            case 1:               b_out = (const float*)d_in[i]; break;
            default: break;
        }
    }
    float* out = (float*)d_out;

    // 1) transpose weights into g_WT (coalesced layout for the scan)
    transpose_w_kernel<<<(K_TOT * 1024 + 255) / 256, 256>>>(w_ih, w_hh);
    // 2) persistent LSTM scan
    lstm_scan_kernel<<<4096 / B_BLK, 256>>>(xd, bias, w_out, b_out, out);
}

// round 13
// speedup vs baseline: 1.9793x; 1.2076x over previous
#include <cuda_runtime.h>

// LSTM_16638703305445: B=4096, T=365, IN=32, H=256, OUT=1
// R11 = R9 design with the macro-expansion bug fixed (SLICE is now an inline
// function; the old macro's parameter `w` captured the `.w` field token).
// W repacked as WT2[(k*256+j)*4+g] -> one coalesced LDG.128 per k-slice,
// 2-slice explicit prefetch ring to cover L2 latency under the 128-reg cap.
// x unified into h_s rows 256..287 (single 288-slice K loop).
// 256 CTAs x 256 threads, 2 CTA/SM.

#define T_STEPS 365
#define IN_DIM  32
#define H_DIM   256
#define B_BLK   16   // batch rows per CTA
#define NB      8    // f32x2 pairs per thread (16 batch rows)
#define K_TOT   (H_DIM + IN_DIM)   // 288
#define K_PAD   4                  // prefetch overrun pad

typedef unsigned long long u64;

// Packed transposed weights: WT2[(k*256 + j)*4 + g]
//   k in [0,256):   w_hh column k      -> w_hh[(g*256+j)*256 + k]
//   k in [256,288): w_ih column k-256  -> w_ih[(g*256+j)*32 + (k-256)]
// Thread j loads float4 at index (k*256 + j) -> fully coalesced LDG.128.
__device__ float g_WT2[(K_TOT + K_PAD) * 1024];

__global__ void transpose_w_kernel(const float* __restrict__ w_ih,
                                   const float* __restrict__ w_hh) {
    int idx = blockIdx.x * blockDim.x + threadIdx.x;
    if (idx >= (K_TOT + K_PAD) * 1024) return;
    int k = idx >> 10;         // 0..291
    int r = idx & 1023;
    int j = r >> 2;            // 0..255
    int g = r & 3;             // gate
    float v = 0.0f;
    if (k < H_DIM)       v = w_hh[(size_t)(g * H_DIM + j) * H_DIM + k];
    else if (k < K_TOT)  v = w_ih[(size_t)(g * H_DIM + j) * IN_DIM + (k - H_DIM)];
    g_WT2[idx] = v;
}

__device__ __forceinline__ u64 fma2(u64 a, u64 b, u64 c) {
    u64 d;
    asm("fma.rn.f32x2 %0, %1, %2, %3;" : "=l"(d) : "l"(a), "l"(b), "l"(c));
    return d;
}
__device__ __forceinline__ u64 bc2(float x) {
    u64 d;
    asm("mov.b64 %0, {%1, %1};" : "=l"(d) : "f"(x));
    return d;
}
__device__ __forceinline__ void unpack2(u64 v, float& lo, float& hi) {
    asm("mov.b64 {%0, %1}, %2;" : "=f"(lo), "=f"(hi) : "l"(v));
}
__device__ __forceinline__ float sigm(float x) {
    return __fdividef(1.0f, 1.0f + __expf(-x));
}
__device__ __forceinline__ float tanh_acc(float x) {
    float a = fabsf(x);
    float e = __expf(-2.0f * a);
    float r = __fdividef(1.0f - e, 1.0f + e);
    return copysignf(r, x);
}

// One k-slice: wv = (wi,wf,wg,wo) already in regs; 4 broadcast LDS.128 for
// the 16 h values; 32 FFMA2.
__device__ __forceinline__ void slice(const float4 wv, const float* hrow,
                                      u64* ai, u64* af, u64* ag, u64* ao) {
    const ulonglong2* hp = (const ulonglong2*)(hrow);
    const ulonglong2 h0 = hp[0], h1 = hp[1], h2 = hp[2], h3 = hp[3];
    const u64 wib = bc2(wv.x), wfb = bc2(wv.y);
    const u64 wgb = bc2(wv.z), wob = bc2(wv.w);
    ai[0] = fma2(h0.x, wib, ai[0]); af[0] = fma2(h0.x, wfb, af[0]);
    ag[0] = fma2(h0.x, wgb, ag[0]); ao[0] = fma2(h0.x, wob, ao[0]);
    ai[1] = fma2(h0.y, wib, ai[1]); af[1] = fma2(h0.y, wfb, af[1]);
    ag[1] = fma2(h0.y, wgb, ag[1]); ao[1] = fma2(h0.y, wob, ao[1]);
    ai[2] = fma2(h1.x, wib, ai[2]); af[2] = fma2(h1.x, wfb, af[2]);
    ag[2] = fma2(h1.x, wgb, ag[2]); ao[2] = fma2(h1.x, wob, ao[2]);
    ai[3] = fma2(h1.y, wib, ai[3]); af[3] = fma2(h1.y, wfb, af[3]);
    ag[3] = fma2(h1.y, wgb, ag[3]); ao[3] = fma2(h1.y, wob, ao[3]);
    ai[4] = fma2(h2.x, wib, ai[4]); af[4] = fma2(h2.x, wfb, af[4]);
    ag[4] = fma2(h2.x, wgb, ag[4]); ao[4] = fma2(h2.x, wob, ao[4]);
    ai[5] = fma2(h2.y, wib, ai[5]); af[5] = fma2(h2.y, wfb, af[5]);
    ag[5] = fma2(h2.y, wgb, ag[5]); ao[5] = fma2(h2.y, wob, ao[5]);
    ai[6] = fma2(h3.x, wib, ai[6]); af[6] = fma2(h3.x, wfb, af[6]);
    ag[6] = fma2(h3.x, wgb, ag[6]); ao[6] = fma2(h3.x, wob, ao[6]);
    ai[7] = fma2(h3.y, wib, ai[7]); af[7] = fma2(h3.y, wfb, af[7]);
    ag[7] = fma2(h3.y, wgb, ag[7]); ao[7] = fma2(h3.y, wob, ao[7]);
}

__global__ void __launch_bounds__(256, 2)
lstm_scan_kernel(const float* __restrict__ xd,    // [B, T, IN]
                 const float* __restrict__ bias,  // [4H]
                 const float* __restrict__ w_out, // [1, H]
                 const float* __restrict__ b_out, // [1]
                 float* __restrict__ out)         // [B, 1]
{
    // rows 0..255 = h state; rows 256..287 = current x tile. [k][b] layout.
    __shared__ float h_s[K_TOT * B_BLK];      // 18 KB
    __shared__ float c_s[B_BLK * H_DIM];      // [b][j], 16 KB, conflict-free

    const int j  = threadIdx.x;          // hidden unit 0..255
    const int B0 = blockIdx.x * B_BLK;   // batch base for this CTA

    #pragma unroll
    for (int b = 0; b < B_BLK; b++) h_s[j * B_BLK + b] = 0.0f;
    #pragma unroll
    for (int b = 0; b < B_BLK; b++) c_s[b * H_DIM + j] = 0.0f;

    const float bi = bias[j];
    const float bf = bias[H_DIM + j];
    const float bg = bias[2 * H_DIM + j];
    const float bo = bias[3 * H_DIM + j];

    // Packed W base: slice k for this thread at Wp[k*256].
    const float4* Wp = (const float4*)g_WT2 + j;

    // x-tile lane mapping (thread covers elements j and j+256 of the 512-elem tile)
    const int xb0 = j >> 5,         xi0 = j & 31;
    const int xb1 = (j + 256) >> 5, xi1 = (j + 256) & 31;
    const float* xp0 = xd + (size_t)(B0 + xb0) * (T_STEPS * IN_DIM) + xi0;
    const float* xp1 = xd + (size_t)(B0 + xb1) * (T_STEPS * IN_DIM) + xi1;

    float xr0 = __ldg(xp0);
    float xr1 = __ldg(xp1);

    __syncthreads();

    for (int t = 0; t < T_STEPS; t++) {
        // stage x(t) into h_s rows 256..287 (transposed to [i][b])
        h_s[(H_DIM + xi0) * B_BLK + xb0] = xr0;
        h_s[(H_DIM + xi1) * B_BLK + xb1] = xr1;
        {   // prefetch x(t+1) — latency hidden under the K loop
            int tn = (t + 1 < T_STEPS) ? t + 1 : t;
            xr0 = __ldg(xp0 + tn * IN_DIM);
            xr1 = __ldg(xp1 + tn * IN_DIM);
        }
        __syncthreads();  // x + previous h ready

        const u64 bi2 = bc2(bi), bf2 = bc2(bf), bg2 = bc2(bg), bo2 = bc2(bo);
        u64 ai[NB], af[NB], ag[NB], ao[NB];
        #pragma unroll
        for (int p = 0; p < NB; p++) { ai[p] = bi2; af[p] = bf2; ag[p] = bg2; ao[p] = bo2; }

        // ---- unified K loop over 288 slices, 2-slice prefetch pipeline
        float4 w0 = __ldg(Wp);
        float4 w1 = __ldg(Wp + 256);
        for (int k0 = 0; k0 < K_TOT; k0 += 2) {
            const float4 n0 = __ldg(Wp + (k0 + 2) * 256);  // pads cover overrun
            const float4 n1 = __ldg(Wp + (k0 + 3) * 256);
            slice(w0, h_s + k0 * B_BLK, ai, af, ag, ao);
            slice(w1, h_s + (k0 + 1) * B_BLK, ai, af, ag, ao);
            w0 = n0; w1 = n1;
        }

        __syncthreads();  // everyone done reading h_s

        // ---- gate nonlinearities + state update + h write (c in smem)
        #pragma unroll
        for (int p = 0; p < NB; p++) {
            float i0, i1, f0, f1, g0, g1, o0, o1;
            unpack2(ai[p], i0, i1);
            unpack2(af[p], f0, f1);
            unpack2(ag[p], g0, g1);
            unpack2(ao[p], o0, o1);
            const int b0 = 2 * p, b1 = 2 * p + 1;
            {
                float iv = sigm(i0), fv = sigm(f0), gv = tanh_acc(g0), ov = sigm(o0);
                float cv = fv * c_s[b0 * H_DIM + j] + iv * gv;
                c_s[b0 * H_DIM + j] = cv;
                h_s[j * B_BLK + b0] = ov * tanh_acc(cv);
            }
            {
                float iv = sigm(i1), fv = sigm(f1), gv = tanh_acc(g1), ov = sigm(o1);
                float cv = fv * c_s[b1 * H_DIM + j] + iv * gv;
                c_s[b1 * H_DIM + j] = cv;
                h_s[j * B_BLK + b1] = ov * tanh_acc(cv);
            }
        }
    }

    __syncthreads();

    // ---- output head: out[b] = relu(sum_k h_T[b,k] * w_out[k] + b_out)
    {
        int b = j >> 4;   // 0..15
        int l = j & 15;   // 0..15
        float s = 0.0f;
        #pragma unroll
        for (int k = l; k < H_DIM; k += 16)
            s += h_s[k * B_BLK + b] * __ldg(&w_out[k]);
        #pragma unroll
        for (int off = 8; off > 0; off >>= 1)
            s += __shfl_down_sync(0xffffffffu, s, off);
        if (l == 0) {
            float r = s + __ldg(&b_out[0]);
            out[B0 + b] = r > 0.0f ? r : 0.0f;
        }
    }
}

extern "C" void kernel_launch(void* const* d_in, const int* in_sizes, int n_in,
                              void* d_out, int out_size) {
    // Identify inputs by element count (all distinct) — robust to ordering.
    const float *xd = nullptr, *w_ih = nullptr, *w_hh = nullptr;
    const float *bias = nullptr, *w_out = nullptr, *b_out = nullptr;
    for (int i = 0; i < n_in; i++) {
        switch (in_sizes[i]) {
            case 4096 * 365 * 32: xd    = (const float*)d_in[i]; break;  // 47841280
            case 1024 * 32:       w_ih  = (const float*)d_in[i]; break;  // 32768
            case 1024 * 256:      w_hh  = (const float*)d_in[i]; break;  // 262144
            case 1024:            bias  = (const float*)d_in[i]; break;
            case 256:             w_out = (const float*)d_in[i]; break;
            case 1:               b_out = (const float*)d_in[i]; break;
            default: break;
        }
    }
    float* out = (float*)d_out;

    // 1) pack weights into WT2 (coalesced float4-per-(k,j) layout)
    transpose_w_kernel<<<((K_TOT + K_PAD) * 1024 + 255) / 256, 256>>>(w_ih, w_hh);
    // 2) persistent LSTM scan
    lstm_scan_kernel<<<4096 / B_BLK, 256>>>(xd, bias, w_out, b_out, out);
}

// round 14
// speedup vs baseline: 2.2091x; 1.1161x over previous
#include <cuda_runtime.h>

// LSTM_16638703305445: B=4096, T=365, IN=32, H=256, OUT=1
// R13: load-balance fix. grid was 256 CTAs over 148 SMs (2-CTA/SM cap) ->
// 108 SMs carried 2 CTAs, 40 carried 1; runtime set by the 2-CTA SMs.
// Now 293 CTAs x 14 batch rows (<= 296 slots) -> uniform 2 CTAs/SM,
// per-SM FFMA2 floor drops 12.5%. Same W layout as R11: WT2[(k*256+j)*4+g],
// one coalesced LDG.128 per k-slice, 2-slice prefetch ring.

#define T_STEPS 365
#define IN_DIM  32
#define H_DIM   256
#define B_TOTAL 4096
#define B_BLK   14   // batch rows per CTA (last CTA: 8 valid)
#define B_STRIDE 16  // padded h_s row stride (16B-aligned vector loads)
#define NB      7    // f32x2 pairs per thread (14 batch rows)
#define K_TOT   (H_DIM + IN_DIM)   // 288
#define K_PAD   4                  // prefetch overrun pad
#define GRID_CTAS ((B_TOTAL + B_BLK - 1) / B_BLK)   // 293

typedef unsigned long long u64;

// Packed transposed weights: WT2[(k*256 + j)*4 + g]
//   k in [0,256):   w_hh column k      -> w_hh[(g*256+j)*256 + k]
//   k in [256,288): w_ih column k-256  -> w_ih[(g*256+j)*32 + (k-256)]
// Thread j loads float4 at index (k*256 + j) -> fully coalesced LDG.128.
__device__ float g_WT2[(K_TOT + K_PAD) * 1024];

__global__ void transpose_w_kernel(const float* __restrict__ w_ih,
                                   const float* __restrict__ w_hh) {
    int idx = blockIdx.x * blockDim.x + threadIdx.x;
    if (idx >= (K_TOT + K_PAD) * 1024) return;
    int k = idx >> 10;         // 0..291
    int r = idx & 1023;
    int j = r >> 2;            // 0..255
    int g = r & 3;             // gate
    float v = 0.0f;
    if (k < H_DIM)       v = w_hh[(size_t)(g * H_DIM + j) * H_DIM + k];
    else if (k < K_TOT)  v = w_ih[(size_t)(g * H_DIM + j) * IN_DIM + (k - H_DIM)];
    g_WT2[idx] = v;
}

__device__ __forceinline__ u64 fma2(u64 a, u64 b, u64 c) {
    u64 d;
    asm("fma.rn.f32x2 %0, %1, %2, %3;" : "=l"(d) : "l"(a), "l"(b), "l"(c));
    return d;
}
__device__ __forceinline__ u64 bc2(float x) {
    u64 d;
    asm("mov.b64 %0, {%1, %1};" : "=l"(d) : "f"(x));
    return d;
}
__device__ __forceinline__ void unpack2(u64 v, float& lo, float& hi) {
    asm("mov.b64 {%0, %1}, %2;" : "=f"(lo), "=f"(hi) : "l"(v));
}
__device__ __forceinline__ float sigm(float x) {
    return __fdividef(1.0f, 1.0f + __expf(-x));
}
__device__ __forceinline__ float tanh_acc(float x) {
    float a = fabsf(x);
    float e = __expf(-2.0f * a);
    float r = __fdividef(1.0f - e, 1.0f + e);
    return copysignf(r, x);
}

// One k-slice: wv = (wi,wf,wg,wo) in regs; 14 h values (3 LDS.128 + 1 LDS.64
// broadcasts); 28 FFMA2.
__device__ __forceinline__ void slice7(const float4 wv, const float* hrow,
                                       u64* ai, u64* af, u64* ag, u64* ao) {
    const ulonglong2* hp = (const ulonglong2*)(hrow);
    const ulonglong2 h0 = hp[0], h1 = hp[1], h2 = hp[2];
    const u64 h3 = *(const u64*)(hrow + 12);
    const u64 wib = bc2(wv.x), wfb = bc2(wv.y);
    const u64 wgb = bc2(wv.z), wob = bc2(wv.w);
    ai[0] = fma2(h0.x, wib, ai[0]); af[0] = fma2(h0.x, wfb, af[0]);
    ag[0] = fma2(h0.x, wgb, ag[0]); ao[0] = fma2(h0.x, wob, ao[0]);
    ai[1] = fma2(h0.y, wib, ai[1]); af[1] = fma2(h0.y, wfb, af[1]);
    ag[1] = fma2(h0.y, wgb, ag[1]); ao[1] = fma2(h0.y, wob, ao[1]);
    ai[2] = fma2(h1.x, wib, ai[2]); af[2] = fma2(h1.x, wfb, af[2]);
    ag[2] = fma2(h1.x, wgb, ag[2]); ao[2] = fma2(h1.x, wob, ao[2]);
    ai[3] = fma2(h1.y, wib, ai[3]); af[3] = fma2(h1.y, wfb, af[3]);
    ag[3] = fma2(h1.y, wgb, ag[3]); ao[3] = fma2(h1.y, wob, ao[3]);
    ai[4] = fma2(h2.x, wib, ai[4]); af[4] = fma2(h2.x, wfb, af[4]);
    ag[4] = fma2(h2.x, wgb, ag[4]); ao[4] = fma2(h2.x, wob, ao[4]);
    ai[5] = fma2(h2.y, wib, ai[5]); af[5] = fma2(h2.y, wfb, af[5]);
    ag[5] = fma2(h2.y, wgb, ag[5]); ao[5] = fma2(h2.y, wob, ao[5]);
    ai[6] = fma2(h3,   wib, ai[6]); af[6] = fma2(h3,   wfb, af[6]);
    ag[6] = fma2(h3,   wgb, ag[6]); ao[6] = fma2(h3,   wob, ao[6]);
}

__global__ void __launch_bounds__(256, 2)
lstm_scan_kernel(const float* __restrict__ xd,    // [B, T, IN]
                 const float* __restrict__ bias,  // [4H]
                 const float* __restrict__ w_out, // [1, H]
                 const float* __restrict__ b_out, // [1]
                 float* __restrict__ out)         // [B, 1]
{
    // rows 0..255 = h state; rows 256..287 = current x tile. [k][b] layout,
    // b-stride padded to 16 for aligned vector LDS (slots 14,15 unused).
    __shared__ float h_s[K_TOT * B_STRIDE];     // 18 KB
    __shared__ float c_s[B_BLK * H_DIM];        // [b][j], 14 KB, conflict-free

    const int j  = threadIdx.x;          // hidden unit 0..255
    const int B0 = blockIdx.x * B_BLK;   // batch base for this CTA

    #pragma unroll
    for (int b = 0; b < B_STRIDE; b++) h_s[j * B_STRIDE + b] = 0.0f;
    #pragma unroll
    for (int b = 0; b < B_BLK; b++) c_s[b * H_DIM + j] = 0.0f;

    const float bi = bias[j];
    const float bf = bias[H_DIM + j];
    const float bg = bias[2 * H_DIM + j];
    const float bo = bias[3 * H_DIM + j];

    // Packed W base: slice k for this thread at Wp[k*256].
    const float4* Wp = (const float4*)g_WT2 + j;

    // x-tile lane mapping: thread covers elements j and j+256 of the
    // (B_BLK*32 = 448)-element tile; element e -> (b = e>>5, i = e&31).
    const int xb0 = j >> 5,         xi0 = j & 31;          // b 0..7, always < B_BLK
    const int xb1 = (j + 256) >> 5, xi1 = (j + 256) & 31;  // b 8..15 (14,15 dead)
    // Clamp global batch row for tail-CTA safety (results discarded via guards).
    const int gr0 = min(B0 + xb0, B_TOTAL - 1);
    const int gr1 = min(B0 + xb1, B_TOTAL - 1);
    const float* xp0 = xd + (size_t)gr0 * (T_STEPS * IN_DIM) + xi0;
    const float* xp1 = xd + (size_t)gr1 * (T_STEPS * IN_DIM) + xi1;

    float xr0 = __ldg(xp0);
    float xr1 = __ldg(xp1);

    __syncthreads();

    for (int t = 0; t < T_STEPS; t++) {
        // stage x(t) into h_s rows 256..287 (transposed to [i][b])
        h_s[(H_DIM + xi0) * B_STRIDE + xb0] = xr0;
        h_s[(H_DIM + xi1) * B_STRIDE + xb1] = xr1;   // slots 14,15 harmless
        {   // prefetch x(t+1) — latency hidden under the K loop
            int tn = (t + 1 < T_STEPS) ? t + 1 : t;
            xr0 = __ldg(xp0 + tn * IN_DIM);
            xr1 = __ldg(xp1 + tn * IN_DIM);
        }
        __syncthreads();  // x + previous h ready

        const u64 bi2 = bc2(bi), bf2 = bc2(bf), bg2 = bc2(bg), bo2 = bc2(bo);
        u64 ai[NB], af[NB], ag[NB], ao[NB];
        #pragma unroll
        for (int p = 0; p < NB; p++) { ai[p] = bi2; af[p] = bf2; ag[p] = bg2; ao[p] = bo2; }

        // ---- unified K loop over 288 slices, 2-slice prefetch pipeline
        float4 w0 = __ldg(Wp);
        float4 w1 = __ldg(Wp + 256);
        for (int k0 = 0; k0 < K_TOT; k0 += 2) {
            const float4 n0 = __ldg(Wp + (k0 + 2) * 256);  // pads cover overrun
            const float4 n1 = __ldg(Wp + (k0 + 3) * 256);
            slice7(w0, h_s + k0 * B_STRIDE, ai, af, ag, ao);
            slice7(w1, h_s + (k0 + 1) * B_STRIDE, ai, af, ag, ao);
            w0 = n0; w1 = n1;
        }

        __syncthreads();  // everyone done reading h_s

        // ---- gate nonlinearities + state update + h write (c in smem)
        #pragma unroll
        for (int p = 0; p < NB; p++) {
            float i0, i1, f0, f1, g0, g1, o0, o1;
            unpack2(ai[p], i0, i1);
            unpack2(af[p], f0, f1);
            unpack2(ag[p], g0, g1);
            unpack2(ao[p], o0, o1);
            const int b0 = 2 * p, b1 = 2 * p + 1;
            {
                float iv = sigm(i0), fv = sigm(f0), gv = tanh_acc(g0), ov = sigm(o0);
                float cv = fv * c_s[b0 * H_DIM + j] + iv * gv;
                c_s[b0 * H_DIM + j] = cv;
                h_s[j * B_STRIDE + b0] = ov * tanh_acc(cv);
            }
            {
                float iv = sigm(i1), fv = sigm(f1), gv = tanh_acc(g1), ov = sigm(o1);
                float cv = fv * c_s[b1 * H_DIM + j] + iv * gv;
                c_s[b1 * H_DIM + j] = cv;
                h_s[j * B_STRIDE + b1] = ov * tanh_acc(cv);
            }
        }
    }

    __syncthreads();

    // ---- output head: out[b] = relu(sum_k h_T[b,k] * w_out[k] + b_out)
    {
        int b = j >> 4;   // 0..15
        int l = j & 15;   // 0..15
        if (b < B_BLK && (B0 + b) < B_TOTAL) {
            float s = 0.0f;
            #pragma unroll
            for (int k = l; k < H_DIM; k += 16)
                s += h_s[k * B_STRIDE + b] * __ldg(&w_out[k]);
            #pragma unroll
            for (int off = 8; off > 0; off >>= 1)
                s += __shfl_down_sync(0xffffffffu, s, off);
            if (l == 0) {
                float r = s + __ldg(&b_out[0]);
                out[B0 + b] = r > 0.0f ? r : 0.0f;
            }
        }
    }
}

extern "C" void kernel_launch(void* const* d_in, const int* in_sizes, int n_in,
                              void* d_out, int out_size) {
    // Identify inputs by element count (all distinct) — robust to ordering.
    const float *xd = nullptr, *w_ih = nullptr, *w_hh = nullptr;
    const float *bias = nullptr, *w_out = nullptr, *b_out = nullptr;
    for (int i = 0; i < n_in; i++) {
        switch (in_sizes[i]) {
            case 4096 * 365 * 32: xd    = (const float*)d_in[i]; break;  // 47841280
            case 1024 * 32:       w_ih  = (const float*)d_in[i]; break;  // 32768
            case 1024 * 256:      w_hh  = (const float*)d_in[i]; break;  // 262144
            case 1024:            bias  = (const float*)d_in[i]; break;
            case 256:             w_out = (const float*)d_in[i]; break;
            case 1:               b_out = (const float*)d_in[i]; break;
            default: break;
        }
    }
    float* out = (float*)d_out;

    // 1) pack weights into WT2 (coalesced float4-per-(k,j) layout)
    transpose_w_kernel<<<((K_TOT + K_PAD) * 1024 + 255) / 256, 256>>>(w_ih, w_hh);
    // 2) persistent LSTM scan, balanced across 148 SMs (2 CTAs/SM)
    lstm_scan_kernel<<<GRID_CTAS, 256>>>(xd, bias, w_out, b_out, out);
}

// round 17
// speedup vs baseline: 2.3696x; 1.0726x over previous
#include <cuda_runtime.h>

// LSTM_16638703305445: B=4096, T=365, IN=32, H=256, OUT=1
// R14: one CTA per SM. 147 CTAs x 256 threads x 28 batch rows,
// __launch_bounds__(256,1) -> 255-reg budget. W (1.18 MB) is now read ONCE
// per SM-step (was twice with 2 CTAs/SM): L2 traffic + LDG issue halved.
// c-state back in registers, 4-slice W prefetch ring, h_s row stride 36
// floats (144B: 16B-aligned LDS.128, epilogue STS conflicts 32-way -> 4-way).
// W layout unchanged: WT2[(k*256+j)*4+g], one coalesced LDG.128 per k-slice.

#define T_STEPS 365
#define IN_DIM  32
#define H_DIM   256
#define B_TOTAL 4096
#define B_BLK   28   // batch rows per CTA (last CTA: 8 valid)
#define B_STRIDE 36  // padded h_s row stride in floats (144B)
#define NB      14   // f32x2 pairs per thread (28 batch rows)
#define K_TOT   (H_DIM + IN_DIM)   // 288
#define K_PAD   8                  // prefetch overrun pad
#define GRID_CTAS ((B_TOTAL + B_BLK - 1) / B_BLK)   // 147

typedef unsigned long long u64;

// Packed transposed weights: WT2[(k*256 + j)*4 + g]
//   k in [0,256):   w_hh column k      -> w_hh[(g*256+j)*256 + k]
//   k in [256,288): w_ih column k-256  -> w_ih[(g*256+j)*32 + (k-256)]
__device__ float g_WT2[(K_TOT + K_PAD) * 1024];

__global__ void transpose_w_kernel(const float* __restrict__ w_ih,
                                   const float* __restrict__ w_hh) {
    int idx = blockIdx.x * blockDim.x + threadIdx.x;
    if (idx >= (K_TOT + K_PAD) * 1024) return;
    int k = idx >> 10;
    int r = idx & 1023;
    int j = r >> 2;
    int g = r & 3;
    float v = 0.0f;
    if (k < H_DIM)       v = w_hh[(size_t)(g * H_DIM + j) * H_DIM + k];
    else if (k < K_TOT)  v = w_ih[(size_t)(g * H_DIM + j) * IN_DIM + (k - H_DIM)];
    g_WT2[idx] = v;
}

__device__ __forceinline__ u64 fma2(u64 a, u64 b, u64 c) {
    u64 d;
    asm("fma.rn.f32x2 %0, %1, %2, %3;" : "=l"(d) : "l"(a), "l"(b), "l"(c));
    return d;
}
__device__ __forceinline__ u64 bc2(float x) {
    u64 d;
    asm("mov.b64 %0, {%1, %1};" : "=l"(d) : "f"(x));
    return d;
}
__device__ __forceinline__ void unpack2(u64 v, float& lo, float& hi) {
    asm("mov.b64 {%0, %1}, %2;" : "=f"(lo), "=f"(hi) : "l"(v));
}
__device__ __forceinline__ float sigm(float x) {
    return __fdividef(1.0f, 1.0f + __expf(-x));
}
__device__ __forceinline__ float tanh_acc(float x) {
    float a = fabsf(x);
    float e = __expf(-2.0f * a);
    float r = __fdividef(1.0f - e, 1.0f + e);
    return copysignf(r, x);
}

// One k-slice: wv = (wi,wf,wg,wo) in regs; 28 h values (7 broadcast LDS.128);
// 56 FFMA2.
__device__ __forceinline__ void slice14(const float4 wv, const float* hrow,
                                        u64* ai, u64* af, u64* ag, u64* ao) {
    const ulonglong2* hp = (const ulonglong2*)(hrow);
    u64 hh[NB];
    #pragma unroll
    for (int q = 0; q < 7; q++) {
        const ulonglong2 hq = hp[q];
        hh[2 * q]     = hq.x;
        hh[2 * q + 1] = hq.y;
    }
    const u64 wib = bc2(wv.x), wfb = bc2(wv.y);
    const u64 wgb = bc2(wv.z), wob = bc2(wv.w);
    #pragma unroll
    for (int p = 0; p < NB; p++) {
        ai[p] = fma2(hh[p], wib, ai[p]);
        af[p] = fma2(hh[p], wfb, af[p]);
        ag[p] = fma2(hh[p], wgb, ag[p]);
        ao[p] = fma2(hh[p], wob, ao[p]);
    }
}

__global__ void __launch_bounds__(256, 1)
lstm_scan_kernel(const float* __restrict__ xd,    // [B, T, IN]
                 const float* __restrict__ bias,  // [4H]
                 const float* __restrict__ w_out, // [1, H]
                 const float* __restrict__ b_out, // [1]
                 float* __restrict__ out)         // [B, 1]
{
    // rows 0..255 = h state; rows 256..287 = current x tile. [k][b] layout,
    // row stride 36 floats (slots 28..35 unused).
    __shared__ float h_s[K_TOT * B_STRIDE];   // 41.5 KB

    const int j  = threadIdx.x;          // hidden unit 0..255
    const int B0 = blockIdx.x * B_BLK;   // batch base for this CTA

    for (int i = j; i < K_TOT * B_STRIDE; i += 256) h_s[i] = 0.0f;

    float c[B_BLK];
    #pragma unroll
    for (int b = 0; b < B_BLK; b++) c[b] = 0.0f;

    const float bi = bias[j];
    const float bf = bias[H_DIM + j];
    const float bg = bias[2 * H_DIM + j];
    const float bo = bias[3 * H_DIM + j];

    const float4* Wp = (const float4*)g_WT2 + j;

    // x-tile: 28 rows x 32 floats = 896 elements; thread covers e = j, j+256,
    // j+512, and (j<128) j+768. e -> (b = e>>5, i = e&31).
    const int eb0 = j >> 5,           ei0 = j & 31;
    const int eb1 = (j + 256) >> 5,   ei1 = (j + 256) & 31;
    const int eb2 = (j + 512) >> 5,   ei2 = (j + 512) & 31;
    const int eb3 = (j + 768) >> 5,   ei3 = (j + 768) & 31;
    const bool has3 = (j < 128);
    const float* xq0 = xd + (size_t)min(B0 + eb0, B_TOTAL - 1) * (T_STEPS * IN_DIM) + ei0;
    const float* xq1 = xd + (size_t)min(B0 + eb1, B_TOTAL - 1) * (T_STEPS * IN_DIM) + ei1;
    const float* xq2 = xd + (size_t)min(B0 + eb2, B_TOTAL - 1) * (T_STEPS * IN_DIM) + ei2;
    const float* xq3 = xd + (size_t)min(B0 + eb3, B_TOTAL - 1) * (T_STEPS * IN_DIM) + ei3;

    float xr0 = __ldg(xq0);
    float xr1 = __ldg(xq1);
    float xr2 = __ldg(xq2);
    float xr3 = has3 ? __ldg(xq3) : 0.0f;

    __syncthreads();

    for (int t = 0; t < T_STEPS; t++) {
        // stage x(t) into h_s rows 256..287 (transposed to [i][b])
        h_s[(H_DIM + ei0) * B_STRIDE + eb0] = xr0;
        h_s[(H_DIM + ei1) * B_STRIDE + eb1] = xr1;
        h_s[(H_DIM + ei2) * B_STRIDE + eb2] = xr2;
        if (has3) h_s[(H_DIM + ei3) * B_STRIDE + eb3] = xr3;
        {   // prefetch x(t+1) — latency hidden under the K loop
            int tn = (t + 1 < T_STEPS) ? t + 1 : t;
            xr0 = __ldg(xq0 + tn * IN_DIM);
            xr1 = __ldg(xq1 + tn * IN_DIM);
            xr2 = __ldg(xq2 + tn * IN_DIM);
            if (has3) xr3 = __ldg(xq3 + tn * IN_DIM);
        }
        __syncthreads();  // x + previous h ready

        const u64 bi2 = bc2(bi), bf2 = bc2(bf), bg2 = bc2(bg), bo2 = bc2(bo);
        u64 ai[NB], af[NB], ag[NB], ao[NB];
        #pragma unroll
        for (int p = 0; p < NB; p++) { ai[p] = bi2; af[p] = bf2; ag[p] = bg2; ao[p] = bo2; }

        // ---- K loop over 288 slices, 4-slice prefetch ring
        float4 w0 = __ldg(Wp);
        float4 w1 = __ldg(Wp + 256);
        float4 w2 = __ldg(Wp + 512);
        float4 w3 = __ldg(Wp + 768);
        for (int k0 = 0; k0 < K_TOT; k0 += 4) {
            const float4 n0 = __ldg(Wp + (k0 + 4) * 256);  // pads cover overrun
            const float4 n1 = __ldg(Wp + (k0 + 5) * 256);
            const float4 n2 = __ldg(Wp + (k0 + 6) * 256);
            const float4 n3 = __ldg(Wp + (k0 + 7) * 256);
            slice14(w0, h_s + (k0 + 0) * B_STRIDE, ai, af, ag, ao);
            slice14(w1, h_s + (k0 + 1) * B_STRIDE, ai, af, ag, ao);
            slice14(w2, h_s + (k0 + 2) * B_STRIDE, ai, af, ag, ao);
            slice14(w3, h_s + (k0 + 3) * B_STRIDE, ai, af, ag, ao);
            w0 = n0; w1 = n1; w2 = n2; w3 = n3;
        }

        __syncthreads();  // everyone done reading h_s

        // ---- gate nonlinearities + state update + h write (c in regs)
        #pragma unroll
        for (int p = 0; p < NB; p++) {
            float i0, i1, f0, f1, g0, g1, o0, o1;
            unpack2(ai[p], i0, i1);
            unpack2(af[p], f0, f1);
            unpack2(ag[p], g0, g1);
            unpack2(ao[p], o0, o1);
            const int b0 = 2 * p, b1 = 2 * p + 1;
            {
                float iv = sigm(i0), fv = sigm(f0), gv = tanh_acc(g0), ov = sigm(o0);
                c[b0] = fv * c[b0] + iv * gv;
                h_s[j * B_STRIDE + b0] = ov * tanh_acc(c[b0]);
            }
            {
                float iv = sigm(i1), fv = sigm(f1), gv = tanh_acc(g1), ov = sigm(o1);
                c[b1] = fv * c[b1] + iv * gv;
                h_s[j * B_STRIDE + b1] = ov * tanh_acc(c[b1]);
            }
        }
    }

    __syncthreads();

    // ---- output head: out[b] = relu(sum_k h_T[b,k] * w_out[k] + b_out)
    {
        int b = j >> 3;   // 0..31
        int l = j & 7;    // 0..7
        if (b < B_BLK && (B0 + b) < B_TOTAL) {
            float s = 0.0f;
            #pragma unroll
            for (int k = l; k < H_DIM; k += 8)
                s += h_s[k * B_STRIDE + b] * __ldg(&w_out[k]);
            #pragma unroll
            for (int off = 4; off > 0; off >>= 1)
                s += __shfl_down_sync(0xffffffffu, s, off, 8);
            if (l == 0) {
                float r = s + __ldg(&b_out[0]);
                out[B0 + b] = r > 0.0f ? r : 0.0f;
            }
        }
    }
}

extern "C" void kernel_launch(void* const* d_in, const int* in_sizes, int n_in,
                              void* d_out, int out_size) {
    // Identify inputs by element count (all distinct) — robust to ordering.
    const float *xd = nullptr, *w_ih = nullptr, *w_hh = nullptr;
    const float *bias = nullptr, *w_out = nullptr, *b_out = nullptr;
    for (int i = 0; i < n_in; i++) {
        switch (in_sizes[i]) {
            case 4096 * 365 * 32: xd    = (const float*)d_in[i]; break;  // 47841280
            case 1024 * 32:       w_ih  = (const float*)d_in[i]; break;  // 32768
            case 1024 * 256:      w_hh  = (const float*)d_in[i]; break;  // 262144
            case 1024:            bias  = (const float*)d_in[i]; break;
            case 256:             w_out = (const float*)d_in[i]; break;
            case 1:               b_out = (const float*)d_in[i]; break;
            default: break;
        }
    }
    float* out = (float*)d_out;

    // 1) pack weights into WT2 (coalesced float4-per-(k,j) layout)
    transpose_w_kernel<<<((K_TOT + K_PAD) * 1024 + 255) / 256, 256>>>(w_ih, w_hh);
    // 2) persistent LSTM scan: one CTA per SM, W read once per SM-step
    lstm_scan_kernel<<<GRID_CTAS, 256>>>(xd, bias, w_out, b_out, out);
}